// round 10
// baseline (speedup 1.0000x reference)
#include <cuda_runtime.h>

// Fixed problem shapes
#define DIMD 272
#define NC   19
#define WCOLS 20                 // padded W cols (10 f32x2 pairs)
#define NPAIR 10
#define ZROWF 32                 // Z row stride floats = 128 B
#define NROWS 65536
#define NISEG 4096
#define THREADS 128
#define RPT 4                    // rows per thread
#define PB_ROWS (THREADS * RPT)  // 512 rows per proj block
#define PROJ_BLOCKS (NROWS / PB_ROWS)   // 128
#define SDW 16                   // d's per stage (272 = 17*16)
#define NSTAGE 17
#define XST 80                   // stage row stride bytes (64 data + 16 pad)
#define STAGE_BYTES (PB_ROWS * XST)     // 40960
#define DEPTH 2
#define WS_BYTES (DIMD * WCOLS * 4)     // 21760
#define SMEM_DYN (DEPTH * STAGE_BYTES + WS_BYTES)  // 103680 -> 2 blocks/SM
#define PPT 16                   // points/thread in bounds part

typedef unsigned long long ull;

__device__ float g_Z[(size_t)NROWS * ZROWF];    // 8 MB, 128B rows
__device__ int   g_off[NISEG + 1];

__device__ __forceinline__ ull pack2(float lo, float hi) {
    ull r; asm("mov.b64 %0, {%1, %2};" : "=l"(r) : "f"(lo), "f"(hi)); return r;
}
__device__ __forceinline__ void unpack2(ull v, float& lo, float& hi) {
    asm("mov.b64 {%0, %1}, %2;" : "=f"(lo), "=f"(hi) : "l"(v));
}
__device__ __forceinline__ void fma2(ull& d, ull a, ull b) {
    asm("fma.rn.f32x2 %0, %1, %2, %0;" : "+l"(d) : "l"(a), "l"(b));
}
__device__ __forceinline__ void add2(ull& d, ull a) {
    asm("add.rn.f32x2 %0, %0, %1;" : "+l"(d) : "l"(a));
}
__device__ __forceinline__ void cpasync16(unsigned smem, const void* g) {
    asm volatile("cp.async.cg.shared.global [%0], [%1], 16;"
                 :: "r"(smem), "l"(g));
}
__device__ __forceinline__ void cpcommit() {
    asm volatile("cp.async.commit_group;");
}
__device__ __forceinline__ void cpwait1() {
    asm volatile("cp.async.wait_group 1;");
}

// ---------------------------------------------------------------------------
// Fat kernel: blocks [0, PROJ_BLOCKS) compute Z = X@W. Coalesced cp.async
// staging (nL=8), 4 rows/thread (8 FFMA2 per W-LDS, 40 indep. acc chains),
// double-buffered. Remaining blocks compute segment boundary offsets.
// ---------------------------------------------------------------------------
__global__ __launch_bounds__(THREADS)
void fat_kernel(const float* __restrict__ X, const float* __restrict__ W,
                const int* __restrict__ segs, int P) {
    extern __shared__ __align__(16) char smem[];
    float* ws = (float*)smem;                 // 21760 B
    char*  xs = smem + WS_BYTES;              // 2 stage buffers

    if (blockIdx.x < PROJ_BLOCKS) {
        const int t = threadIdx.x;
        const int row0 = blockIdx.x * PB_ROWS;
        const char* gX = (const char*)(X + (size_t)row0 * DIMD);

        // Coalesced stage issue: 512 rows x 64 B (64B-aligned: 1088 = 17*64).
        auto issue_stage = [&](int s) {
            unsigned sb = (unsigned)__cvta_generic_to_shared(xs)
                        + (unsigned)((s & 1) * STAGE_BYTES);
            const char* gbase = gX + (size_t)s * 64;
#pragma unroll
            for (int k = 0; k < 16; k++) {
                int i = t + k * THREADS;          // 0..2047
                int r = i >> 2;
                int c = i & 3;
                cpasync16(sb + (unsigned)(r * XST + c * 16),
                          gbase + (size_t)r * (DIMD * 4) + c * 16);
            }
        };

        issue_stage(0); cpcommit();
        issue_stage(1); cpcommit();

        // Stage W (padded to 20 cols) while cp.asyncs fly
        for (int i = t; i < DIMD * WCOLS; i += THREADS) {
            int dd = i / WCOLS, c = i - dd * WCOLS;
            ws[i] = (c < NC) ? W[dd * NC + c] : 0.f;
        }

        ull acc[RPT][NPAIR];
        const ull z2 = pack2(0.f, 0.f);
#pragma unroll
        for (int r = 0; r < RPT; r++)
#pragma unroll
            for (int j = 0; j < NPAIR; j++) acc[r][j] = z2;

        for (int s = 0; s < NSTAGE; s++) {
            cpwait1();            // stage s resident (only newest may pend)
            __syncthreads();      // stage s + ws visible to all

            const char* sbase = xs + (s & 1) * STAGE_BYTES;
            const float4* xp[RPT];
#pragma unroll
            for (int r = 0; r < RPT; r++)
                xp[r] = (const float4*)(sbase + (t + r * THREADS) * XST);
            const ulonglong2* wq = (const ulonglong2*)(ws + s * SDW * WCOLS);

#pragma unroll
            for (int k = 0; k < 4; k++) {
                float4 xv[RPT];
#pragma unroll
                for (int r = 0; r < RPT; r++) xv[r] = xp[r][k];  // LDS.128
                float xf[RPT][4];
#pragma unroll
                for (int r = 0; r < RPT; r++) {
                    xf[r][0] = xv[r].x; xf[r][1] = xv[r].y;
                    xf[r][2] = xv[r].z; xf[r][3] = xv[r].w;
                }
#pragma unroll
                for (int m = 0; m < 4; m++) {
                    int dd = k * 4 + m;
                    ull xr[RPT];
#pragma unroll
                    for (int r = 0; r < RPT; r++)
                        xr[r] = pack2(xf[r][m], xf[r][m]);
#pragma unroll
                    for (int jj = 0; jj < 5; jj++) {
                        ulonglong2 w = wq[dd * 5 + jj];   // LDS.128 broadcast
#pragma unroll
                        for (int r = 0; r < RPT; r++) {
                            fma2(acc[r][2 * jj],     xr[r], w.x);
                            fma2(acc[r][2 * jj + 1], xr[r], w.y);
                        }
                    }
                }
            }

            __syncthreads();      // all reads of buffer (s&1) done
            if (s + 2 < NSTAGE) { issue_stage(s + 2); }
            cpcommit();           // unconditional: uniform group count
        }

#pragma unroll
        for (int r = 0; r < RPT; r++) {
            ulonglong2* za =
                (ulonglong2*)&g_Z[(size_t)(row0 + t + r * THREADS) * ZROWF];
#pragma unroll
            for (int jj = 0; jj < 5; jj++) {
                ulonglong2 sa;
                sa.x = acc[r][2 * jj]; sa.y = acc[r][2 * jj + 1];
                za[jj] = sa;
            }
        }
    } else {
        // ----------------- segment bounds part -----------------
        const int base = (blockIdx.x - PROJ_BLOCKS) * (THREADS * PPT)
                       + threadIdx.x * PPT;
        if (base >= P) return;
        int vv[PPT];
        const int4* s4 = (const int4*)(segs + base);
#pragma unroll
        for (int q = 0; q < PPT / 4; q++) {
            int4 v = __ldg(s4 + q);
            vv[q*4+0] = v.x; vv[q*4+1] = v.y; vv[q*4+2] = v.z; vv[q*4+3] = v.w;
        }
        int prev = (base == 0) ? -1 : __ldg(segs + base - 1);
#pragma unroll
        for (int k = 0; k < PPT; k++) {
            int s = vv[k];
            if (s != prev)
                for (int q = prev + 1; q <= s; q++) g_off[q] = base + k;
            prev = s;
        }
        if (base + PPT >= P)
            for (int q = prev + 1; q <= NISEG; q++) g_off[q] = P;
    }
}

// ---------------------------------------------------------------------------
// Seg kernel (round-8 proven version): 2 warps/segment, 3 groups x 10
// pair-lanes, MLP-4 batches, shfl + shared combine; mean + bias + sigmoid.
// ---------------------------------------------------------------------------
__global__ __launch_bounds__(256)
void seg_kernel(const int* __restrict__ pidx, const float* __restrict__ bias,
                float* __restrict__ out) {
    const int t = threadIdx.x;
    const int w = t >> 5;
    const int lane = t & 31;
    const int h = w & 1;
    const int s = blockIdx.x * 4 + (w >> 1);

    const int start = __ldg(&g_off[s]);
    const int end   = __ldg(&g_off[s + 1]);

    const int g = lane / NPAIR;          // 0..2 active; lanes 30,31 idle
    const int j = lane - g * NPAIR;

    __shared__ ull sAcc[8 * NPAIR];

    ull acc0 = 0, acc1 = 0;
    if (g < 3) {
        int p = start + 3 * h + g;       // stride 6 across both warps
        for (; p + 18 < end; p += 24) {
            int r0 = __ldg(pidx + p);
            int r1 = __ldg(pidx + p + 6);
            int r2 = __ldg(pidx + p + 12);
            int r3 = __ldg(pidx + p + 18);
            ull v0 = *(const ull*)&g_Z[(size_t)r0 * ZROWF + 2 * j];
            ull v1 = *(const ull*)&g_Z[(size_t)r1 * ZROWF + 2 * j];
            ull v2 = *(const ull*)&g_Z[(size_t)r2 * ZROWF + 2 * j];
            ull v3 = *(const ull*)&g_Z[(size_t)r3 * ZROWF + 2 * j];
            add2(acc0, v0); add2(acc1, v1);
            add2(acc0, v2); add2(acc1, v3);
        }
        for (; p < end; p += 6) {
            int r = __ldg(pidx + p);
            ull v = *(const ull*)&g_Z[(size_t)r * ZROWF + 2 * j];
            add2(acc0, v);
        }
        add2(acc0, acc1);
    }

    ull v1 = __shfl_down_sync(0xffffffffu, acc0, 10);
    ull v2 = __shfl_down_sync(0xffffffffu, acc0, 20);
    add2(acc0, v1);
    add2(acc0, v2);

    if (lane < NPAIR) sAcc[w * NPAIR + lane] = acc0;
    __syncthreads();

    if (h == 0 && lane < NPAIR) {
        ull total = sAcc[w * NPAIR + lane];
        add2(total, sAcc[(w + 1) * NPAIR + lane]);
        float f0, f1; unpack2(total, f0, f1);
        float cnt = (float)(end - start);
        float inv = 1.0f / fmaxf(cnt, 1.0f);
        int c0 = 2 * lane;
        float x0 = f0 * inv + __ldg(bias + c0);
        out[(size_t)s * NC + c0] = 1.0f / (1.0f + __expf(-x0));
        if (c0 + 1 < NC) {
            float x1 = f1 * inv + __ldg(bias + c0 + 1);
            out[(size_t)s * NC + c0 + 1] = 1.0f / (1.0f + __expf(-x1));
        }
    }
}

// ---------------------------------------------------------------------------
extern "C" void kernel_launch(void* const* d_in, const int* in_sizes, int n_in,
                              void* d_out, int out_size) {
    const float* X    = (const float*)d_in[0];
    const float* W    = (const float*)d_in[1];
    const float* b    = (const float*)d_in[2];
    const int*   pidx = (const int*)d_in[3];
    const int*   segs = (const int*)d_in[4];
    float*       out  = (float*)d_out;

    const int P = in_sizes[3];
    const int boundsBlocks = (P + THREADS * PPT - 1) / (THREADS * PPT);

    static int attr_done = 0;
    if (!attr_done) {
        cudaFuncSetAttribute(fat_kernel,
                             cudaFuncAttributeMaxDynamicSharedMemorySize,
                             SMEM_DYN);
        attr_done = 1;
    }

    fat_kernel<<<PROJ_BLOCKS + boundsBlocks, THREADS, SMEM_DYN>>>(X, W, segs, P);
    seg_kernel<<<NISEG / 4, 256>>>(pidx, b, out);
}

// round 11
// speedup vs baseline: 1.3775x; 1.3775x over previous
#include <cuda_runtime.h>

// Fixed problem shapes
#define DIMD 272
#define NC   19
#define WN   24                  // padded W cols for 3 n-tiles of 8
#define NPAIR 10
#define ZROWF 32                 // Z row stride floats = 128 B
#define NROWS 65536
#define NISEG 4096
#define THREADS 128
#define MTILE 16
#define WARPS 4
#define TB_ROWS (MTILE * WARPS)          // 64 rows per proj block
#define PROJ_BLOCKS (NROWS / TB_ROWS)    // 1024
#define KSTEPS (DIMD / 8)                // 34
#define PPT 16                   // points/thread in bounds part

typedef unsigned long long ull;

__device__ float g_Z[(size_t)NROWS * ZROWF];    // 8 MB, 128B rows
__device__ int   g_off[NISEG + 1];

__device__ __forceinline__ ull pack2(float lo, float hi) {
    ull r; asm("mov.b64 %0, {%1, %2};" : "=l"(r) : "f"(lo), "f"(hi)); return r;
}
__device__ __forceinline__ void unpack2(ull v, float& lo, float& hi) {
    asm("mov.b64 {%0, %1}, %2;" : "=f"(lo), "=f"(hi) : "l"(v));
}
__device__ __forceinline__ void add2(ull& d, ull a) {
    asm("add.rn.f32x2 %0, %0, %1;" : "+l"(d) : "l"(a));
}
__device__ __forceinline__ unsigned f2tf32(float f) {
    unsigned u; asm("cvt.rna.tf32.f32 %0, %1;" : "=r"(u) : "f"(f)); return u;
}
__device__ __forceinline__ void mma_tf32(float* d, unsigned a0, unsigned a1,
                                         unsigned a2, unsigned a3,
                                         unsigned b0, unsigned b1) {
    asm volatile(
        "mma.sync.aligned.m16n8k8.row.col.f32.tf32.tf32.f32 "
        "{%0,%1,%2,%3}, {%4,%5,%6,%7}, {%8,%9}, {%0,%1,%2,%3};"
        : "+f"(d[0]), "+f"(d[1]), "+f"(d[2]), "+f"(d[3])
        : "r"(a0), "r"(a1), "r"(a2), "r"(a3), "r"(b0), "r"(b1));
}

// ---------------------------------------------------------------------------
// Fat kernel: blocks [0, PROJ_BLOCKS) compute Z = X@W with tf32 mma.sync
// (m16n8k8, 1 M-tile/warp, N padded to 24 = 3 n-tiles, K = 34 steps of 8).
// Remaining blocks compute segment boundary offsets.
// ---------------------------------------------------------------------------
__global__ __launch_bounds__(THREADS)
void fat_kernel(const float* __restrict__ X, const float* __restrict__ W,
                const int* __restrict__ segs, int P) {
    if (blockIdx.x < PROJ_BLOCKS) {
        __shared__ unsigned ws[DIMD * WN];   // tf32-converted padded W, 26 KB

        const int t = threadIdx.x;
        // Stage W -> tf32 in shared
        for (int i = t; i < DIMD * WN; i += THREADS) {
            int dd = i / WN, c = i - dd * WN;
            float v = (c < NC) ? W[dd * NC + c] : 0.f;
            ws[i] = f2tf32(v);
        }
        __syncthreads();

        const int warp = t >> 5;
        const int lane = t & 31;
        const int qrow = lane >> 2;          // 0..7
        const int qcol = lane & 3;           // 0..3
        const int row0 = blockIdx.x * TB_ROWS + warp * MTILE;

        const float* x0 = X + (size_t)(row0 + qrow) * DIMD + qcol;
        const float* x1 = x0 + 8 * DIMD;

        float d[3][4];
#pragma unroll
        for (int n = 0; n < 3; n++)
#pragma unroll
            for (int q = 0; q < 4; q++) d[n][q] = 0.f;

#pragma unroll 2
        for (int k = 0; k < KSTEPS; k++) {
            const int kc = k * 8;
            // A fragment (rows qrow, qrow+8; cols kc+qcol, kc+qcol+4)
            unsigned a0 = f2tf32(__ldg(x0 + kc));
            unsigned a1 = f2tf32(__ldg(x1 + kc));
            unsigned a2 = f2tf32(__ldg(x0 + kc + 4));
            unsigned a3 = f2tf32(__ldg(x1 + kc + 4));

            // B fragments: b0 = W[kc+qcol][n0 + lane/4], b1 = +4 k-rows
            const unsigned* wb = ws + (kc + qcol) * WN + qrow;
#pragma unroll
            for (int n = 0; n < 3; n++) {
                unsigned b0 = wb[n * 8];
                unsigned b1 = wb[n * 8 + 4 * WN];
                mma_tf32(d[n], a0, a1, a2, a3, b0, b1);
            }
        }

        // Epilogue: c0,c1 -> row qrow cols 2*qcol,+1 ; c2,c3 -> row qrow+8
        const int r0 = row0 + qrow;
        const int r1 = r0 + 8;
#pragma unroll
        for (int n = 0; n < 3; n++) {
            int c = n * 8 + qcol * 2;
            *(float2*)&g_Z[(size_t)r0 * ZROWF + c] = make_float2(d[n][0], d[n][1]);
            *(float2*)&g_Z[(size_t)r1 * ZROWF + c] = make_float2(d[n][2], d[n][3]);
        }
    } else {
        // ----------------- segment bounds part -----------------
        const int base = (blockIdx.x - PROJ_BLOCKS) * (THREADS * PPT)
                       + threadIdx.x * PPT;
        if (base >= P) return;
        int vv[PPT];
        const int4* s4 = (const int4*)(segs + base);
#pragma unroll
        for (int q = 0; q < PPT / 4; q++) {
            int4 v = __ldg(s4 + q);
            vv[q*4+0] = v.x; vv[q*4+1] = v.y; vv[q*4+2] = v.z; vv[q*4+3] = v.w;
        }
        int prev = (base == 0) ? -1 : __ldg(segs + base - 1);
#pragma unroll
        for (int k = 0; k < PPT; k++) {
            int s = vv[k];
            if (s != prev)
                for (int q = prev + 1; q <= s; q++) g_off[q] = base + k;
            prev = s;
        }
        if (base + PPT >= P)
            for (int q = prev + 1; q <= NISEG; q++) g_off[q] = P;
    }
}

// ---------------------------------------------------------------------------
// Seg kernel (round-8 proven): 2 warps/segment, 3 groups x 10 pair-lanes,
// MLP-4 batches, shfl + shared combine; mean + bias + sigmoid.
// ---------------------------------------------------------------------------
__global__ __launch_bounds__(256)
void seg_kernel(const int* __restrict__ pidx, const float* __restrict__ bias,
                float* __restrict__ out) {
    const int t = threadIdx.x;
    const int w = t >> 5;
    const int lane = t & 31;
    const int h = w & 1;
    const int s = blockIdx.x * 4 + (w >> 1);

    const int start = __ldg(&g_off[s]);
    const int end   = __ldg(&g_off[s + 1]);

    const int g = lane / NPAIR;          // 0..2 active; lanes 30,31 idle
    const int j = lane - g * NPAIR;

    __shared__ ull sAcc[8 * NPAIR];

    ull acc0 = 0, acc1 = 0;
    if (g < 3) {
        int p = start + 3 * h + g;       // stride 6 across both warps
        for (; p + 18 < end; p += 24) {
            int r0 = __ldg(pidx + p);
            int r1 = __ldg(pidx + p + 6);
            int r2 = __ldg(pidx + p + 12);
            int r3 = __ldg(pidx + p + 18);
            ull v0 = *(const ull*)&g_Z[(size_t)r0 * ZROWF + 2 * j];
            ull v1 = *(const ull*)&g_Z[(size_t)r1 * ZROWF + 2 * j];
            ull v2 = *(const ull*)&g_Z[(size_t)r2 * ZROWF + 2 * j];
            ull v3 = *(const ull*)&g_Z[(size_t)r3 * ZROWF + 2 * j];
            add2(acc0, v0); add2(acc1, v1);
            add2(acc0, v2); add2(acc1, v3);
        }
        for (; p < end; p += 6) {
            int r = __ldg(pidx + p);
            ull v = *(const ull*)&g_Z[(size_t)r * ZROWF + 2 * j];
            add2(acc0, v);
        }
        add2(acc0, acc1);
    }

    ull v1 = __shfl_down_sync(0xffffffffu, acc0, 10);
    ull v2 = __shfl_down_sync(0xffffffffu, acc0, 20);
    add2(acc0, v1);
    add2(acc0, v2);

    if (lane < NPAIR) sAcc[w * NPAIR + lane] = acc0;
    __syncthreads();

    if (h == 0 && lane < NPAIR) {
        ull total = sAcc[w * NPAIR + lane];
        add2(total, sAcc[(w + 1) * NPAIR + lane]);
        float f0, f1; unpack2(total, f0, f1);
        float cnt = (float)(end - start);
        float inv = 1.0f / fmaxf(cnt, 1.0f);
        int c0 = 2 * lane;
        float x0 = f0 * inv + __ldg(bias + c0);
        out[(size_t)s * NC + c0] = 1.0f / (1.0f + __expf(-x0));
        if (c0 + 1 < NC) {
            float x1 = f1 * inv + __ldg(bias + c0 + 1);
            out[(size_t)s * NC + c0 + 1] = 1.0f / (1.0f + __expf(-x1));
        }
    }
}

// ---------------------------------------------------------------------------
extern "C" void kernel_launch(void* const* d_in, const int* in_sizes, int n_in,
                              void* d_out, int out_size) {
    const float* X    = (const float*)d_in[0];
    const float* W    = (const float*)d_in[1];
    const float* b    = (const float*)d_in[2];
    const int*   pidx = (const int*)d_in[3];
    const int*   segs = (const int*)d_in[4];
    float*       out  = (float*)d_out;

    const int P = in_sizes[3];
    const int boundsBlocks = (P + THREADS * PPT - 1) / (THREADS * PPT);

    fat_kernel<<<PROJ_BLOCKS + boundsBlocks, THREADS>>>(X, W, segs, P);
    seg_kernel<<<NISEG / 4, 256>>>(pidx, b, out);
}

// round 12
// speedup vs baseline: 1.6987x; 1.2332x over previous
#include <cuda_runtime.h>

// Fixed problem shapes
#define DIMD 272
#define NC   19
#define WN   24                  // padded W cols = 3 n-tiles of 8
#define NPAIR 10
#define ZROWF 32                 // Z row stride floats = 128 B
#define NROWS 65536
#define NISEG 4096
#define THREADS 128
#define WARPS 4
#define TB_ROWS 64               // rows per proj block (16/warp)
#define PROJ_BLOCKS (NROWS / TB_ROWS)    // 1024
#define NSTAGE 17                // 272 cols = 17 chunks of 16
#define XST 80                   // stage row stride bytes (64 data + 16 pad)
#define STAGE_BYTES (TB_ROWS * XST)      // 5120
#define PPT 16                   // points/thread in bounds part

typedef unsigned long long ull;

__device__ float g_Z[(size_t)NROWS * ZROWF];    // 8 MB, 128B rows
__device__ int   g_off[NISEG + 1];

__device__ __forceinline__ ull pack2(float lo, float hi) {
    ull r; asm("mov.b64 %0, {%1, %2};" : "=l"(r) : "f"(lo), "f"(hi)); return r;
}
__device__ __forceinline__ void unpack2(ull v, float& lo, float& hi) {
    asm("mov.b64 {%0, %1}, %2;" : "=f"(lo), "=f"(hi) : "l"(v));
}
__device__ __forceinline__ void add2(ull& d, ull a) {
    asm("add.rn.f32x2 %0, %0, %1;" : "+l"(d) : "l"(a));
}
__device__ __forceinline__ unsigned f2tf32(float f) {
    unsigned u; asm("cvt.rna.tf32.f32 %0, %1;" : "=r"(u) : "f"(f)); return u;
}
__device__ __forceinline__ void mma_tf32(float* d, unsigned a0, unsigned a1,
                                         unsigned a2, unsigned a3,
                                         unsigned b0, unsigned b1) {
    asm volatile(
        "mma.sync.aligned.m16n8k8.row.col.f32.tf32.tf32.f32 "
        "{%0,%1,%2,%3}, {%4,%5,%6,%7}, {%8,%9}, {%0,%1,%2,%3};"
        : "+f"(d[0]), "+f"(d[1]), "+f"(d[2]), "+f"(d[3])
        : "r"(a0), "r"(a1), "r"(a2), "r"(a3), "r"(b0), "r"(b1));
}
__device__ __forceinline__ void cpasync16(unsigned smem, const void* g) {
    asm volatile("cp.async.cg.shared.global [%0], [%1], 16;"
                 :: "r"(smem), "l"(g));
}
__device__ __forceinline__ void cpcommit() {
    asm volatile("cp.async.commit_group;");
}
__device__ __forceinline__ void cpwait1() {
    asm volatile("cp.async.wait_group 1;");
}

// ---------------------------------------------------------------------------
// Fat kernel: blocks [0, PROJ_BLOCKS) compute Z = X@W with tf32 mma.sync fed
// from COALESCED cp.async-staged shared tiles (nL=8 per copy instr,
// conflict-free LDS for both A and B fragments). Remaining blocks compute
// segment boundary offsets.
// ---------------------------------------------------------------------------
__global__ __launch_bounds__(THREADS)
void fat_kernel(const float* __restrict__ X, const float* __restrict__ W,
                const int* __restrict__ segs, int P) {
    if (blockIdx.x < PROJ_BLOCKS) {
        __shared__ __align__(16) unsigned ws[DIMD * WN];     // 26112 B, tf32 W
        __shared__ __align__(16) char xs[2 * STAGE_BYTES];   // 10240 B

        const int t = threadIdx.x;
        const int row0 = blockIdx.x * TB_ROWS;
        const char* gX = (const char*)(X + (size_t)row0 * DIMD);
        const unsigned xsb = (unsigned)__cvta_generic_to_shared(xs);

        // Coalesced stage issue: 64 rows x 64 B; 2 cp.async.16 per thread.
        // (1088 = 17*64, so every 64-B chunk is 64-B aligned in gmem.)
        auto issue_stage = [&](int s) {
            unsigned sb = xsb + (unsigned)((s & 1) * STAGE_BYTES);
            const char* gbase = gX + (size_t)s * 64;
#pragma unroll
            for (int k = 0; k < 2; k++) {
                int i = t + k * THREADS;       // 0..255
                int r = i >> 2;
                int c = i & 3;
                cpasync16(sb + (unsigned)(r * XST + c * 16),
                          gbase + (size_t)r * (DIMD * 4) + c * 16);
            }
        };

        issue_stage(0); cpcommit();
        issue_stage(1); cpcommit();

        // Stage W -> tf32 in shared while cp.asyncs fly
        for (int i = t; i < DIMD * WN; i += THREADS) {
            int dd = i / WN, c = i - dd * WN;
            float v = (c < NC) ? W[dd * NC + c] : 0.f;
            ws[i] = f2tf32(v);
        }

        const int warp = t >> 5;
        const int lane = t & 31;
        const int qrow = lane >> 2;           // 0..7
        const int qcol = lane & 3;            // 0..3

        float d[3][4];
#pragma unroll
        for (int n = 0; n < 3; n++)
#pragma unroll
            for (int q = 0; q < 4; q++) d[n][q] = 0.f;

        for (int s = 0; s < NSTAGE; s++) {
            cpwait1();            // stage s resident (only newest may pend)
            __syncthreads();      // stage + ws visible to all

            const char* sbase = xs + (s & 1) * STAGE_BYTES;
            // A rows for this warp: warp*16 + qrow and +8 (conflict-free:
            // bank = (20r + c) mod 32 distinct over the warp)
            const float* ar0 = (const float*)
                (sbase + (warp * 16 + qrow) * XST) + qcol;
            const float* ar1 = (const float*)
                (sbase + (warp * 16 + qrow + 8) * XST) + qcol;

#pragma unroll
            for (int ks = 0; ks < 2; ks++) {
                const int co = ks * 8;
                unsigned a0 = f2tf32(ar0[co]);
                unsigned a1 = f2tf32(ar1[co]);
                unsigned a2 = f2tf32(ar0[co + 4]);
                unsigned a3 = f2tf32(ar1[co + 4]);

                const int kc = s * 16 + co;
                const unsigned* wb = ws + (kc + qcol) * WN + qrow;
#pragma unroll
                for (int n = 0; n < 3; n++) {
                    unsigned b0 = wb[n * 8];
                    unsigned b1 = wb[n * 8 + 4 * WN];
                    mma_tf32(d[n], a0, a1, a2, a3, b0, b1);
                }
            }

            __syncthreads();      // all reads of buffer (s&1) done
            if (s + 2 < NSTAGE) issue_stage(s + 2);
            cpcommit();           // unconditional: uniform group count
        }

        // Epilogue: d[n][0,1] -> row qrow cols n*8+2*qcol ; d[n][2,3] -> +8
        const int r0 = row0 + warp * 16 + qrow;
        const int r1 = r0 + 8;
#pragma unroll
        for (int n = 0; n < 3; n++) {
            int c = n * 8 + qcol * 2;
            *(float2*)&g_Z[(size_t)r0 * ZROWF + c] =
                make_float2(d[n][0], d[n][1]);
            *(float2*)&g_Z[(size_t)r1 * ZROWF + c] =
                make_float2(d[n][2], d[n][3]);
        }
    } else {
        // ----------------- segment bounds part -----------------
        const int base = (blockIdx.x - PROJ_BLOCKS) * (THREADS * PPT)
                       + threadIdx.x * PPT;
        if (base >= P) return;
        int vv[PPT];
        const int4* s4 = (const int4*)(segs + base);
#pragma unroll
        for (int q = 0; q < PPT / 4; q++) {
            int4 v = __ldg(s4 + q);
            vv[q*4+0] = v.x; vv[q*4+1] = v.y; vv[q*4+2] = v.z; vv[q*4+3] = v.w;
        }
        int prev = (base == 0) ? -1 : __ldg(segs + base - 1);
#pragma unroll
        for (int k = 0; k < PPT; k++) {
            int s = vv[k];
            if (s != prev)
                for (int q = prev + 1; q <= s; q++) g_off[q] = base + k;
            prev = s;
        }
        if (base + PPT >= P)
            for (int q = prev + 1; q <= NISEG; q++) g_off[q] = P;
    }
}

// ---------------------------------------------------------------------------
// Seg kernel (round-8 proven): 2 warps/segment, 3 groups x 10 pair-lanes,
// MLP-4 batches, shfl + shared combine; mean + bias + sigmoid.
// ---------------------------------------------------------------------------
__global__ __launch_bounds__(256)
void seg_kernel(const int* __restrict__ pidx, const float* __restrict__ bias,
                float* __restrict__ out) {
    const int t = threadIdx.x;
    const int w = t >> 5;
    const int lane = t & 31;
    const int h = w & 1;
    const int s = blockIdx.x * 4 + (w >> 1);

    const int start = __ldg(&g_off[s]);
    const int end   = __ldg(&g_off[s + 1]);

    const int g = lane / NPAIR;          // 0..2 active; lanes 30,31 idle
    const int j = lane - g * NPAIR;

    __shared__ ull sAcc[8 * NPAIR];

    ull acc0 = 0, acc1 = 0;
    if (g < 3) {
        int p = start + 3 * h + g;       // stride 6 across both warps
        for (; p + 18 < end; p += 24) {
            int r0 = __ldg(pidx + p);
            int r1 = __ldg(pidx + p + 6);
            int r2 = __ldg(pidx + p + 12);
            int r3 = __ldg(pidx + p + 18);
            ull v0 = *(const ull*)&g_Z[(size_t)r0 * ZROWF + 2 * j];
            ull v1 = *(const ull*)&g_Z[(size_t)r1 * ZROWF + 2 * j];
            ull v2 = *(const ull*)&g_Z[(size_t)r2 * ZROWF + 2 * j];
            ull v3 = *(const ull*)&g_Z[(size_t)r3 * ZROWF + 2 * j];
            add2(acc0, v0); add2(acc1, v1);
            add2(acc0, v2); add2(acc1, v3);
        }
        for (; p < end; p += 6) {
            int r = __ldg(pidx + p);
            ull v = *(const ull*)&g_Z[(size_t)r * ZROWF + 2 * j];
            add2(acc0, v);
        }
        add2(acc0, acc1);
    }

    ull v1 = __shfl_down_sync(0xffffffffu, acc0, 10);
    ull v2 = __shfl_down_sync(0xffffffffu, acc0, 20);
    add2(acc0, v1);
    add2(acc0, v2);

    if (lane < NPAIR) sAcc[w * NPAIR + lane] = acc0;
    __syncthreads();

    if (h == 0 && lane < NPAIR) {
        ull total = sAcc[w * NPAIR + lane];
        add2(total, sAcc[(w + 1) * NPAIR + lane]);
        float f0, f1; unpack2(total, f0, f1);
        float cnt = (float)(end - start);
        float inv = 1.0f / fmaxf(cnt, 1.0f);
        int c0 = 2 * lane;
        float x0 = f0 * inv + __ldg(bias + c0);
        out[(size_t)s * NC + c0] = 1.0f / (1.0f + __expf(-x0));
        if (c0 + 1 < NC) {
            float x1 = f1 * inv + __ldg(bias + c0 + 1);
            out[(size_t)s * NC + c0 + 1] = 1.0f / (1.0f + __expf(-x1));
        }
    }
}

// ---------------------------------------------------------------------------
extern "C" void kernel_launch(void* const* d_in, const int* in_sizes, int n_in,
                              void* d_out, int out_size) {
    const float* X    = (const float*)d_in[0];
    const float* W    = (const float*)d_in[1];
    const float* b    = (const float*)d_in[2];
    const int*   pidx = (const int*)d_in[3];
    const int*   segs = (const int*)d_in[4];
    float*       out  = (float*)d_out;

    const int P = in_sizes[3];
    const int boundsBlocks = (P + THREADS * PPT - 1) / (THREADS * PPT);

    fat_kernel<<<PROJ_BLOCKS + boundsBlocks, THREADS>>>(X, W, segs, P);
    seg_kernel<<<NISEG / 4, 256>>>(pidx, b, out);
}